// round 2
// baseline (speedup 1.0000x reference)
#include <cuda_runtime.h>

// ---------------- problem constants ----------------
#define U_CNT 100000
#define SI_CNT 50000
#define TI_CNT 40000
#define DD 64
#define BB 8192
#define NS (U_CNT + SI_CNT)   // 150000 rows in source graph
#define NT (U_CNT + TI_CNT)   // 140000 rows in target graph
#define NSW ((NS + 31) / 32)  // bitmap words
#define NTW ((NT + 31) / 32)
#define SLOTS 64              // accumulator sharding to avoid same-address atomic serialization

// ---------------- device scratch (static, no allocs) ----------------
__device__ float g_agg_s_int[(size_t)NS * DD];
__device__ float g_agg_s_pop[(size_t)NS * DD];
__device__ float g_agg_t_int[(size_t)NT * DD];
__device__ float g_agg_t_pop[(size_t)NT * DD];
__device__ unsigned g_need_s[NSW];
__device__ unsigned g_need_t[NTW];
__device__ double g_accs[12 * SLOTS];
__device__ int g_cnts[3 * SLOTS];

// ---------------- helpers ----------------
__device__ __forceinline__ float wred(float v) {
#pragma unroll
    for (int o = 16; o; o >>= 1) v += __shfl_xor_sync(0xffffffffu, v, o);
    return v;
}

// numerically stable log_sigmoid
__device__ __forceinline__ float lsig(float x) {
    return fminf(x, 0.0f) - log1pf(expf(-fabsf(x)));
}

// vector reduction: 16B atomic add (sm_90+); dst must be 16B aligned
__device__ __forceinline__ void red_add_f4(float* p, float a, float b, float c, float d) {
    asm volatile(
        "{\n\t.reg .u64 q;\n\t"
        "cvta.to.global.u64 q, %0;\n\t"
        "red.global.add.v4.f32 [q], {%1,%2,%3,%4};\n\t}"
        :: "l"(p), "f"(a), "f"(b), "f"(c), "f"(d) : "memory");
}

// ---------------- kernels ----------------
__global__ void k_clear() {
    int i = blockIdx.x * blockDim.x + threadIdx.x;
    if (i < NSW) g_need_s[i] = 0u;
    if (i < NTW) g_need_t[i] = 0u;
    if (i < 12 * SLOTS) g_accs[i] = 0.0;
    if (i < 3 * SLOTS) g_cnts[i] = 0;
}

__global__ void k_bitmap(const int* __restrict__ user, const int* __restrict__ sp,
                         const int* __restrict__ sn, const int* __restrict__ tp,
                         const int* __restrict__ tn) {
    int i = blockIdx.x * blockDim.x + threadIdx.x;
    if (i >= 5 * BB) return;
    int which = i / BB, j = i - which * BB;
    if (which == 0) {
        int u = user[j];
        atomicOr(&g_need_s[(unsigned)u >> 5], 1u << (u & 31));
        atomicOr(&g_need_t[(unsigned)u >> 5], 1u << (u & 31));
    } else if (which == 1) {
        int r = U_CNT + sp[j];
        atomicOr(&g_need_s[(unsigned)r >> 5], 1u << (r & 31));
    } else if (which == 2) {
        int r = U_CNT + sn[j];
        atomicOr(&g_need_s[(unsigned)r >> 5], 1u << (r & 31));
    } else if (which == 3) {
        int r = U_CNT + tp[j];
        atomicOr(&g_need_t[(unsigned)r >> 5], 1u << (r & 31));
    } else {
        int r = U_CNT + tn[j];
        atomicOr(&g_need_t[(unsigned)r >> 5], 1u << (r & 31));
    }
}

// zero only the agg rows we will read (one warp per row; lanes split int/pop halves)
__global__ void k_zero_rows() {
    int gw = (blockIdx.x * blockDim.x + threadIdx.x) >> 5;
    int lane = threadIdx.x & 31;
    int half = lane >> 4, sub = lane & 15;
    float4 z = make_float4(0.f, 0.f, 0.f, 0.f);
    if (gw < NS) {
        if ((g_need_s[(unsigned)gw >> 5] >> (gw & 31)) & 1u) {
            float* base = half ? g_agg_s_pop : g_agg_s_int;
            ((float4*)(base + (size_t)gw * DD))[sub] = z;
        }
    } else {
        int r = gw - NS;
        if (r < NT && ((g_need_t[(unsigned)r >> 5] >> (r & 31)) & 1u)) {
            float* base = half ? g_agg_t_pop : g_agg_t_int;
            ((float4*)(base + (size_t)r * DD))[sub] = z;
        }
    }
}

// filtered COO scatter: one thread per edge scans, warp ballot-compacts the
// ~15% of edges whose destination row is needed; whole warp processes each
// hit edge (lanes 0-15 -> int factor, 16-31 -> pop factor, float4 per lane).
__global__ void k_edges(const int* __restrict__ rows, const int* __restrict__ cols,
                        const float* __restrict__ vals, const float* __restrict__ dint,
                        const float* __restrict__ dpop,
                        const float* __restrict__ u_int, const float* __restrict__ i_int,
                        const float* __restrict__ u_pop, const float* __restrict__ i_pop,
                        int nnz, int is_s) {
    const unsigned* __restrict__ need = is_s ? g_need_s : g_need_t;
    float* agg_i = is_s ? g_agg_s_int : g_agg_t_int;
    float* agg_p = is_s ? g_agg_s_pop : g_agg_t_pop;

    int idx = blockIdx.x * blockDim.x + threadIdx.x;
    int lane = threadIdx.x & 31;
    int r = 0, c = 0;
    float wi = 0.f, wp = 0.f;
    bool act = false;
    if (idx < nnz) {
        r = rows[idx];
        act = (need[(unsigned)r >> 5] >> (r & 31)) & 1u;
        if (act) {
            c = cols[idx];
            float v = vals[idx];
            wi = v * dint[idx];
            wp = v * dpop[idx];
        }
    }
    unsigned m = __ballot_sync(0xffffffffu, act);
    int half = lane >> 4, sub = lane & 15;
    while (m) {
        int src = __ffs(m) - 1;
        m &= m - 1u;
        int er = __shfl_sync(0xffffffffu, r, src);
        int ec = __shfl_sync(0xffffffffu, c, src);
        float ewi = __shfl_sync(0xffffffffu, wi, src);
        float ewp = __shfl_sync(0xffffffffu, wp, src);
        float w = half ? ewp : ewi;
        const float* tab = half ? (ec < U_CNT ? u_pop : i_pop)
                                : (ec < U_CNT ? u_int : i_int);
        int cr = (ec < U_CNT) ? ec : ec - U_CNT;
        float4 e = ((const float4*)(tab + (size_t)cr * DD))[sub];
        float* dst = (half ? agg_p : agg_i) + (size_t)er * DD + sub * 4;
        red_add_f4(dst, w * e.x, w * e.y, w * e.z, w * e.w);
    }
}

// one warp per sample: 12 gathered vectors, 8 dots, 8 loss contributions
// masks read as 32-bit words: nonzero == true (works for int32 0/1 AND float32 0.0/1.0)
__global__ void k_loss(const int* __restrict__ user, const int* __restrict__ spi,
                       const int* __restrict__ sni, const int* __restrict__ tpi,
                       const int* __restrict__ tni,
                       const unsigned* __restrict__ mask_s,
                       const unsigned* __restrict__ mask_t,
                       const float* __restrict__ su_i, const float* __restrict__ si_i,
                       const float* __restrict__ tu_i, const float* __restrict__ ti_i,
                       const float* __restrict__ su_p, const float* __restrict__ si_p,
                       const float* __restrict__ tu_p, const float* __restrict__ ti_p) {
    int w = (blockIdx.x * blockDim.x + threadIdx.x) >> 5;
    int lane = threadIdx.x & 31;
    if (w >= BB) return;
    int u = user[w], ps = spi[w], ns = sni[w], pt = tpi[w], nt = tni[w];

#define GET2(t, row) (((const float2*)((t) + (size_t)(row) * DD))[lane])
    auto mk = [](float2 a, float2 b) {
        return make_float2(0.5f * (a.x + b.x), 0.5f * (a.y + b.y));
    };
    auto d2 = [](float2 a, float2 b) { return a.x * b.x + a.y * b.y; };

    float2 usi = mk(GET2(su_i, u), GET2(g_agg_s_int, u));
    float2 usp = mk(GET2(su_p, u), GET2(g_agg_s_pop, u));
    float2 uti = mk(GET2(tu_i, u), GET2(g_agg_t_int, u));
    float2 utp = mk(GET2(tu_p, u), GET2(g_agg_t_pop, u));
    float2 ipi = mk(GET2(si_i, ps), GET2(g_agg_s_int, U_CNT + ps));
    float2 ini = mk(GET2(si_i, ns), GET2(g_agg_s_int, U_CNT + ns));
    float2 ipp = mk(GET2(si_p, ps), GET2(g_agg_s_pop, U_CNT + ps));
    float2 inp2 = mk(GET2(si_p, ns), GET2(g_agg_s_pop, U_CNT + ns));
    float2 jpi = mk(GET2(ti_i, pt), GET2(g_agg_t_int, U_CNT + pt));
    float2 jni = mk(GET2(ti_i, nt), GET2(g_agg_t_int, U_CNT + nt));
    float2 jpp = mk(GET2(ti_p, pt), GET2(g_agg_t_pop, U_CNT + pt));
    float2 jnp2 = mk(GET2(ti_p, nt), GET2(g_agg_t_pop, U_CNT + nt));
#undef GET2

    float sp_i = wred(d2(usi, ipi)), sn_i = wred(d2(usi, ini));
    float sp_p = wred(d2(usp, ipp)), sn_p = wred(d2(usp, inp2));
    float tp_i = wred(d2(uti, jpi)), tn_i = wred(d2(uti, jni));
    float tp_p = wred(d2(utp, jpp)), tn_p = wred(d2(utp, jnp2));

    if (lane == 0) {
        int slot = w & (SLOTS - 1);
        float mS = (mask_s[w] != 0u) ? 1.f : 0.f;
        float mT = (mask_t[w] != 0u) ? 1.f : 0.f;
        atomicAdd(&g_accs[0 * SLOTS + slot], (double)(mS * lsig(sp_i - sn_i)));
        atomicAdd(&g_accs[1 * SLOTS + slot], (double)(mS * lsig(sn_p - sp_p)));
        atomicAdd(&g_accs[2 * SLOTS + slot], (double)((1.f - mS) * lsig(sp_p - sn_p)));
        atomicAdd(&g_accs[3 * SLOTS + slot], (double)(mT * lsig(tp_i - tn_i)));
        atomicAdd(&g_accs[4 * SLOTS + slot], (double)(mT * lsig(tn_p - tp_p)));
        atomicAdd(&g_accs[5 * SLOTS + slot], (double)((1.f - mT) * lsig(tp_p - tn_p)));
        atomicAdd(&g_accs[6 * SLOTS + slot], (double)lsig((sp_i + sp_p) - (sn_i + sn_p)));
        atomicAdd(&g_accs[7 * SLOTS + slot], (double)lsig((tp_i + tp_p) - (tn_i + tn_p)));
    }
}

// masked L1 terms: one warp per row over combined space [U | SI | TI]
__global__ void k_dis(const float* __restrict__ su_i, const float* __restrict__ su_p,
                      const float* __restrict__ tu_i, const float* __restrict__ tu_p,
                      const float* __restrict__ si_i, const float* __restrict__ si_p,
                      const float* __restrict__ ti_i, const float* __restrict__ ti_p) {
    int gw = (blockIdx.x * blockDim.x + threadIdx.x) >> 5;
    int lane = threadIdx.x & 31;
    int slot = gw & (SLOTS - 1);
    if (gw < U_CNT) {
        int r = gw;
        if ((g_need_s[(unsigned)r >> 5] >> (r & 31)) & 1u) {
            float2 a = ((const float2*)(su_i + (size_t)r * DD))[lane];
            float2 b = ((const float2*)(su_p + (size_t)r * DD))[lane];
            float2 c = ((const float2*)(tu_i + (size_t)r * DD))[lane];
            float2 d = ((const float2*)(tu_p + (size_t)r * DD))[lane];
            float s1 = fabsf(a.x - b.x) + fabsf(a.y - b.y);
            float s2 = fabsf(c.x - d.x) + fabsf(c.y - d.y);
            s1 = wred(s1);
            s2 = wred(s2);
            if (lane == 0) {
                atomicAdd(&g_accs[8 * SLOTS + slot], (double)s1);
                atomicAdd(&g_accs[10 * SLOTS + slot], (double)s2);
                atomicAdd(&g_cnts[0 * SLOTS + slot], 1);
            }
        }
    } else if (gw < U_CNT + SI_CNT) {
        int r = gw;  // row index in source graph == gw
        int it = gw - U_CNT;
        if ((g_need_s[(unsigned)r >> 5] >> (r & 31)) & 1u) {
            float2 a = ((const float2*)(si_i + (size_t)it * DD))[lane];
            float2 b = ((const float2*)(si_p + (size_t)it * DD))[lane];
            float s = wred(fabsf(a.x - b.x) + fabsf(a.y - b.y));
            if (lane == 0) {
                atomicAdd(&g_accs[9 * SLOTS + slot], (double)s);
                atomicAdd(&g_cnts[1 * SLOTS + slot], 1);
            }
        }
    } else if (gw < U_CNT + SI_CNT + TI_CNT) {
        int it = gw - U_CNT - SI_CNT;
        int r = U_CNT + it;
        if ((g_need_t[(unsigned)r >> 5] >> (r & 31)) & 1u) {
            float2 a = ((const float2*)(ti_i + (size_t)it * DD))[lane];
            float2 b = ((const float2*)(ti_p + (size_t)it * DD))[lane];
            float s = wred(fabsf(a.x - b.x) + fabsf(a.y - b.y));
            if (lane == 0) {
                atomicAdd(&g_accs[11 * SLOTS + slot], (double)s);
                atomicAdd(&g_cnts[2 * SLOTS + slot], 1);
            }
        }
    }
}

__global__ void k_final(float* out) {
    double a[12];
#pragma unroll
    for (int i = 0; i < 12; i++) {
        double s = 0.0;
        for (int j = 0; j < SLOTS; j++) s += g_accs[i * SLOTS + j];
        a[i] = s;
    }
    int c[3];
#pragma unroll
    for (int i = 0; i < 3; i++) {
        int s = 0;
        for (int j = 0; j < SLOTS; j++) s += g_cnts[i * SLOTS + j];
        c[i] = s;
    }
    double Bn = (double)BB;
    double li_s = -a[0] / Bn, lp_s = -(a[1] + a[2]) / Bn;
    double li_t = -a[3] / Bn, lp_t = -(a[4] + a[5]) / Bn;
    double lt_s = -a[6] / Bn, lt_t = -a[7] / Bn;
    double cu = (double)(c[0] > 1 ? c[0] : 1);
    double cs = (double)(c[1] > 1 ? c[1] : 1);
    double ct = (double)(c[2] > 1 ? c[2] : 1);
    double dis = a[8] / (cu * DD) + a[9] / (cs * DD) + a[10] / (cu * DD) + a[11] / (ct * DD);
    double loss = lt_s + lt_t + 0.1 * (li_s + li_t) + 0.1 * (lp_s + lp_t) - 0.01 * dis;
    out[0] = (float)loss;
}

// ---------------- launch ----------------
extern "C" void kernel_launch(void* const* d_in, const int* in_sizes, int n_in,
                              void* d_out, int out_size) {
    const int* user = (const int*)d_in[0];
    const int* src_pos = (const int*)d_in[1];
    const int* src_neg = (const int*)d_in[2];
    const int* tgt_pos = (const int*)d_in[3];
    const int* tgt_neg = (const int*)d_in[4];
    const unsigned* mask_s = (const unsigned*)d_in[5];
    const unsigned* mask_t = (const unsigned*)d_in[6];
    const float* su_int = (const float*)d_in[7];
    const float* si_int = (const float*)d_in[8];
    const float* tu_int = (const float*)d_in[9];
    const float* ti_int = (const float*)d_in[10];
    const float* su_pop = (const float*)d_in[11];
    const float* si_pop = (const float*)d_in[12];
    const float* tu_pop = (const float*)d_in[13];
    const float* ti_pop = (const float*)d_in[14];
    const int* s_rows = (const int*)d_in[15];
    const int* s_cols = (const int*)d_in[16];
    const float* s_vals = (const float*)d_in[17];
    const int* t_rows = (const int*)d_in[18];
    const int* t_cols = (const int*)d_in[19];
    const float* t_vals = (const float*)d_in[20];
    const float* drop_s_int = (const float*)d_in[21];
    const float* drop_t_int = (const float*)d_in[22];
    const float* drop_s_pop = (const float*)d_in[23];
    const float* drop_t_pop = (const float*)d_in[24];

    int nnz_s = in_sizes[15];
    int nnz_t = in_sizes[18];

    k_clear<<<(NSW + 255) / 256, 256>>>();
    k_bitmap<<<(5 * BB + 255) / 256, 256>>>(user, src_pos, src_neg, tgt_pos, tgt_neg);
    // warp per row: 8 warps/block of 256 threads
    k_zero_rows<<<(NS + NT + 7) / 8, 256>>>();
    k_edges<<<(nnz_s + 255) / 256, 256>>>(s_rows, s_cols, s_vals, drop_s_int, drop_s_pop,
                                          su_int, si_int, su_pop, si_pop, nnz_s, 1);
    k_edges<<<(nnz_t + 255) / 256, 256>>>(t_rows, t_cols, t_vals, drop_t_int, drop_t_pop,
                                          tu_int, ti_int, tu_pop, ti_pop, nnz_t, 0);
    k_loss<<<BB / 8, 256>>>(user, src_pos, src_neg, tgt_pos, tgt_neg, mask_s, mask_t,
                            su_int, si_int, tu_int, ti_int, su_pop, si_pop, tu_pop, ti_pop);
    k_dis<<<(U_CNT + SI_CNT + TI_CNT + 7) / 8, 256>>>(su_int, su_pop, tu_int, tu_pop,
                                                      si_int, si_pop, ti_int, ti_pop);
    k_final<<<1, 1>>>((float*)d_out);
}

// round 3
// speedup vs baseline: 1.1070x; 1.1070x over previous
#include <cuda_runtime.h>

// ---------------- problem constants ----------------
#define U_CNT 100000
#define SI_CNT 50000
#define TI_CNT 40000
#define DD 64
#define BB 8192
#define NS (U_CNT + SI_CNT)   // 150000 rows in source graph
#define NT (U_CNT + TI_CNT)   // 140000 rows in target graph
#define NSW ((NS + 31) / 32)  // bitmap words
#define NTW ((NT + 31) / 32)
#define SLOTS 64

// ---------------- device scratch ----------------
__device__ float g_agg_s_int[(size_t)NS * DD];
__device__ float g_agg_s_pop[(size_t)NS * DD];
__device__ float g_agg_t_int[(size_t)NT * DD];
__device__ float g_agg_t_pop[(size_t)NT * DD];
__device__ unsigned g_need_s[NSW];
__device__ unsigned g_need_t[NTW];
__device__ double g_accs[12 * SLOTS];
__device__ int g_cnts[3 * SLOTS];
__device__ unsigned g_done = 0;

// ---------------- helpers ----------------
__device__ __forceinline__ float wred(float v) {
#pragma unroll
    for (int o = 16; o; o >>= 1) v += __shfl_xor_sync(0xffffffffu, v, o);
    return v;
}
__device__ __forceinline__ double wredd(double v) {
#pragma unroll
    for (int o = 16; o; o >>= 1) v += __shfl_xor_sync(0xffffffffu, v, o);
    return v;
}
__device__ __forceinline__ int wredi(int v) {
#pragma unroll
    for (int o = 16; o; o >>= 1) v += __shfl_xor_sync(0xffffffffu, v, o);
    return v;
}
__device__ __forceinline__ float lsig(float x) {
    return fminf(x, 0.0f) - log1pf(expf(-fabsf(x)));
}
__device__ __forceinline__ void red_add_f4(float* p, float a, float b, float c, float d) {
    asm volatile(
        "{\n\t.reg .u64 q;\n\t"
        "cvta.to.global.u64 q, %0;\n\t"
        "red.global.add.v4.f32 [q], {%1,%2,%3,%4};\n\t}"
        :: "l"(p), "f"(a), "f"(b), "f"(c), "f"(d) : "memory");
}

// ---------------- kernels ----------------
__global__ void k_clear() {
    int i = blockIdx.x * blockDim.x + threadIdx.x;
    if (i < NSW) g_need_s[i] = 0u;
    if (i < NTW) g_need_t[i] = 0u;
    if (i < 12 * SLOTS) g_accs[i] = 0.0;
    if (i < 3 * SLOTS) g_cnts[i] = 0;
}

__global__ void k_bitmap(const int* __restrict__ user, const int* __restrict__ sp,
                         const int* __restrict__ sn, const int* __restrict__ tp,
                         const int* __restrict__ tn) {
    int i = blockIdx.x * blockDim.x + threadIdx.x;
    if (i >= 5 * BB) return;
    int which = i / BB, j = i - which * BB;
    if (which == 0) {
        int u = user[j];
        atomicOr(&g_need_s[(unsigned)u >> 5], 1u << (u & 31));
        atomicOr(&g_need_t[(unsigned)u >> 5], 1u << (u & 31));
    } else if (which == 1) {
        int r = U_CNT + sp[j];
        atomicOr(&g_need_s[(unsigned)r >> 5], 1u << (r & 31));
    } else if (which == 2) {
        int r = U_CNT + sn[j];
        atomicOr(&g_need_s[(unsigned)r >> 5], 1u << (r & 31));
    } else if (which == 3) {
        int r = U_CNT + tp[j];
        atomicOr(&g_need_t[(unsigned)r >> 5], 1u << (r & 31));
    } else {
        int r = U_CNT + tn[j];
        atomicOr(&g_need_t[(unsigned)r >> 5], 1u << (r & 31));
    }
}

// warp per bitmap word: ffs-loop over set bits, whole warp zeroes one row
// (lanes 0-15 -> int factor float4s, lanes 16-31 -> pop factor)
__global__ void __launch_bounds__(256) k_zero_rows() {
    int gw = (blockIdx.x * blockDim.x + threadIdx.x) >> 5;
    int lane = threadIdx.x & 31;
    int half = lane >> 4, sub = lane & 15;
    float4 z = make_float4(0.f, 0.f, 0.f, 0.f);
    unsigned word;
    float* agg_i;
    float* agg_p;
    int rbase;
    if (gw < NSW) {
        word = g_need_s[gw];
        agg_i = g_agg_s_int; agg_p = g_agg_s_pop;
        rbase = gw * 32;
    } else if (gw < NSW + NTW) {
        word = g_need_t[gw - NSW];
        agg_i = g_agg_t_int; agg_p = g_agg_t_pop;
        rbase = (gw - NSW) * 32;
    } else return;
    while (word) {
        int b = __ffs(word) - 1;
        word &= word - 1u;
        int row = rbase + b;
        float* base = half ? agg_p : agg_i;
        ((float4*)(base + (size_t)row * DD))[sub] = z;
    }
}

// fused filtered COO scatter over BOTH graphs; 2-edge unrolled ballot loop.
__global__ void __launch_bounds__(256) k_edges_all(
    const int* __restrict__ rows_s, const int* __restrict__ cols_s,
    const float* __restrict__ vals_s, const float* __restrict__ dsi,
    const float* __restrict__ dsp,
    const int* __restrict__ rows_t, const int* __restrict__ cols_t,
    const float* __restrict__ vals_t, const float* __restrict__ dti,
    const float* __restrict__ dtp,
    const float* __restrict__ su_i, const float* __restrict__ si_i,
    const float* __restrict__ su_p, const float* __restrict__ si_p,
    const float* __restrict__ tu_i, const float* __restrict__ ti_i,
    const float* __restrict__ tu_p, const float* __restrict__ ti_p,
    int nnz_s, int nnz_t, int blocks_s) {

    bool is_s = (int)blockIdx.x < blocks_s;
    int bblk = is_s ? blockIdx.x : blockIdx.x - blocks_s;
    int idx = bblk * 256 + threadIdx.x;
    int nnz = is_s ? nnz_s : nnz_t;

    const int* __restrict__ rows = is_s ? rows_s : rows_t;
    const int* __restrict__ cols = is_s ? cols_s : cols_t;
    const float* __restrict__ vals = is_s ? vals_s : vals_t;
    const float* __restrict__ dint = is_s ? dsi : dti;
    const float* __restrict__ dpop = is_s ? dsp : dtp;
    const unsigned* __restrict__ need = is_s ? g_need_s : g_need_t;
    float* agg_i = is_s ? g_agg_s_int : g_agg_t_int;
    float* agg_p = is_s ? g_agg_s_pop : g_agg_t_pop;
    const float* __restrict__ u_i = is_s ? su_i : tu_i;
    const float* __restrict__ i_i = is_s ? si_i : ti_i;
    const float* __restrict__ u_p = is_s ? su_p : tu_p;
    const float* __restrict__ i_p = is_s ? si_p : ti_p;

    int lane = threadIdx.x & 31;
    int half = lane >> 4, sub = lane & 15;

    int r = 0, c = 0;
    float wi = 0.f, wp = 0.f;
    bool act = false;
    if (idx < nnz) {
        // all loads coalesced and independent (no post-ballot dependent loads)
        r = rows[idx];
        c = cols[idx];
        float v = vals[idx];
        wi = v * dint[idx];
        wp = v * dpop[idx];
        act = (need[(unsigned)r >> 5] >> (r & 31)) & 1u;
    }
    unsigned m = __ballot_sync(0xffffffffu, act);
    while (m) {
        int s0 = __ffs(m) - 1;
        m &= m - 1u;
        int s1 = -1;
        if (m) { s1 = __ffs(m) - 1; m &= m - 1u; }

        int er0 = __shfl_sync(0xffffffffu, r, s0);
        int ec0 = __shfl_sync(0xffffffffu, c, s0);
        float w0 = half ? __shfl_sync(0xffffffffu, wp, s0)
                        : __shfl_sync(0xffffffffu, wi, s0);
        const float* tab0 = half ? (ec0 < U_CNT ? u_p : i_p)
                                 : (ec0 < U_CNT ? u_i : i_i);
        int cr0 = (ec0 < U_CNT) ? ec0 : ec0 - U_CNT;
        float4 e0 = __ldg(((const float4*)(tab0 + (size_t)cr0 * DD)) + sub);
        float* dst0 = (half ? agg_p : agg_i) + (size_t)er0 * DD + sub * 4;

        if (s1 >= 0) {
            int er1 = __shfl_sync(0xffffffffu, r, s1);
            int ec1 = __shfl_sync(0xffffffffu, c, s1);
            float w1 = half ? __shfl_sync(0xffffffffu, wp, s1)
                            : __shfl_sync(0xffffffffu, wi, s1);
            const float* tab1 = half ? (ec1 < U_CNT ? u_p : i_p)
                                     : (ec1 < U_CNT ? u_i : i_i);
            int cr1 = (ec1 < U_CNT) ? ec1 : ec1 - U_CNT;
            float4 e1 = __ldg(((const float4*)(tab1 + (size_t)cr1 * DD)) + sub);
            float* dst1 = (half ? agg_p : agg_i) + (size_t)er1 * DD + sub * 4;
            red_add_f4(dst0, w0 * e0.x, w0 * e0.y, w0 * e0.z, w0 * e0.w);
            red_add_f4(dst1, w1 * e1.x, w1 * e1.y, w1 * e1.z, w1 * e1.w);
        } else {
            red_add_f4(dst0, w0 * e0.x, w0 * e0.y, w0 * e0.z, w0 * e0.w);
        }
    }
}

// fused: loss (blocks [0,1024)) + dis (rest) + final reduction by last block
#define LOSS_BLOCKS (BB / 8)
__global__ void __launch_bounds__(256) k_loss_dis_final(
    const int* __restrict__ user, const int* __restrict__ spi,
    const int* __restrict__ sni, const int* __restrict__ tpi,
    const int* __restrict__ tni,
    const unsigned* __restrict__ mask_s, const unsigned* __restrict__ mask_t,
    const float* __restrict__ su_i, const float* __restrict__ si_i,
    const float* __restrict__ tu_i, const float* __restrict__ ti_i,
    const float* __restrict__ su_p, const float* __restrict__ si_p,
    const float* __restrict__ tu_p, const float* __restrict__ ti_p,
    float* __restrict__ out) {

    int lane = threadIdx.x & 31;
    int wid = threadIdx.x >> 5;
    __shared__ double s_rows[12];
    __shared__ int s_cnt[3];
    __shared__ int s_last;

    if ((int)blockIdx.x < LOSS_BLOCKS) {
        int w = blockIdx.x * 8 + wid;
        int u = user[w], ps = spi[w], ns = sni[w], pt = tpi[w], nt = tni[w];

#define GET2(t, row) (((const float2*)((t) + (size_t)(row) * DD))[lane])
        auto mk = [](float2 a, float2 b) {
            return make_float2(0.5f * (a.x + b.x), 0.5f * (a.y + b.y));
        };
        auto d2 = [](float2 a, float2 b) { return a.x * b.x + a.y * b.y; };

        float2 usi = mk(GET2(su_i, u), GET2(g_agg_s_int, u));
        float2 usp = mk(GET2(su_p, u), GET2(g_agg_s_pop, u));
        float2 uti = mk(GET2(tu_i, u), GET2(g_agg_t_int, u));
        float2 utp = mk(GET2(tu_p, u), GET2(g_agg_t_pop, u));
        float2 ipi = mk(GET2(si_i, ps), GET2(g_agg_s_int, U_CNT + ps));
        float2 ini = mk(GET2(si_i, ns), GET2(g_agg_s_int, U_CNT + ns));
        float2 ipp = mk(GET2(si_p, ps), GET2(g_agg_s_pop, U_CNT + ps));
        float2 inp2 = mk(GET2(si_p, ns), GET2(g_agg_s_pop, U_CNT + ns));
        float2 jpi = mk(GET2(ti_i, pt), GET2(g_agg_t_int, U_CNT + pt));
        float2 jni = mk(GET2(ti_i, nt), GET2(g_agg_t_int, U_CNT + nt));
        float2 jpp = mk(GET2(ti_p, pt), GET2(g_agg_t_pop, U_CNT + pt));
        float2 jnp2 = mk(GET2(ti_p, nt), GET2(g_agg_t_pop, U_CNT + nt));
#undef GET2

        float sp_i = wred(d2(usi, ipi)), sn_i = wred(d2(usi, ini));
        float sp_p = wred(d2(usp, ipp)), sn_p = wred(d2(usp, inp2));
        float tp_i = wred(d2(uti, jpi)), tn_i = wred(d2(uti, jni));
        float tp_p = wred(d2(utp, jpp)), tn_p = wred(d2(utp, jnp2));

        if (lane == 0) {
            int slot = w & (SLOTS - 1);
            float mS = (mask_s[w] != 0u) ? 1.f : 0.f;
            float mT = (mask_t[w] != 0u) ? 1.f : 0.f;
            atomicAdd(&g_accs[0 * SLOTS + slot], (double)(mS * lsig(sp_i - sn_i)));
            atomicAdd(&g_accs[1 * SLOTS + slot], (double)(mS * lsig(sn_p - sp_p)));
            atomicAdd(&g_accs[2 * SLOTS + slot], (double)((1.f - mS) * lsig(sp_p - sn_p)));
            atomicAdd(&g_accs[3 * SLOTS + slot], (double)(mT * lsig(tp_i - tn_i)));
            atomicAdd(&g_accs[4 * SLOTS + slot], (double)(mT * lsig(tn_p - tp_p)));
            atomicAdd(&g_accs[5 * SLOTS + slot], (double)((1.f - mT) * lsig(tp_p - tn_p)));
            atomicAdd(&g_accs[6 * SLOTS + slot], (double)lsig((sp_i + sp_p) - (sn_i + sn_p)));
            atomicAdd(&g_accs[7 * SLOTS + slot], (double)lsig((tp_i + tp_p) - (tn_i + tn_p)));
        }
    } else {
        int gw = (blockIdx.x - LOSS_BLOCKS) * 8 + wid;
        int slot = gw & (SLOTS - 1);
        if (gw < U_CNT) {
            int rr = gw;
            if ((g_need_s[(unsigned)rr >> 5] >> (rr & 31)) & 1u) {
                float2 a = ((const float2*)(su_i + (size_t)rr * DD))[lane];
                float2 b = ((const float2*)(su_p + (size_t)rr * DD))[lane];
                float2 cc = ((const float2*)(tu_i + (size_t)rr * DD))[lane];
                float2 d = ((const float2*)(tu_p + (size_t)rr * DD))[lane];
                float s1 = wred(fabsf(a.x - b.x) + fabsf(a.y - b.y));
                float s2 = wred(fabsf(cc.x - d.x) + fabsf(cc.y - d.y));
                if (lane == 0) {
                    atomicAdd(&g_accs[8 * SLOTS + slot], (double)s1);
                    atomicAdd(&g_accs[10 * SLOTS + slot], (double)s2);
                    atomicAdd(&g_cnts[0 * SLOTS + slot], 1);
                }
            }
        } else if (gw < U_CNT + SI_CNT) {
            int it = gw - U_CNT;
            if ((g_need_s[(unsigned)gw >> 5] >> (gw & 31)) & 1u) {
                float2 a = ((const float2*)(si_i + (size_t)it * DD))[lane];
                float2 b = ((const float2*)(si_p + (size_t)it * DD))[lane];
                float s = wred(fabsf(a.x - b.x) + fabsf(a.y - b.y));
                if (lane == 0) {
                    atomicAdd(&g_accs[9 * SLOTS + slot], (double)s);
                    atomicAdd(&g_cnts[1 * SLOTS + slot], 1);
                }
            }
        } else if (gw < U_CNT + SI_CNT + TI_CNT) {
            int it = gw - U_CNT - SI_CNT;
            int rr = U_CNT + it;
            if ((g_need_t[(unsigned)rr >> 5] >> (rr & 31)) & 1u) {
                float2 a = ((const float2*)(ti_i + (size_t)it * DD))[lane];
                float2 b = ((const float2*)(ti_p + (size_t)it * DD))[lane];
                float s = wred(fabsf(a.x - b.x) + fabsf(a.y - b.y));
                if (lane == 0) {
                    atomicAdd(&g_accs[11 * SLOTS + slot], (double)s);
                    atomicAdd(&g_cnts[2 * SLOTS + slot], 1);
                }
            }
        }
    }

    // ---- last-block final reduction ----
    __syncthreads();
    if (threadIdx.x == 0) {
        __threadfence();
        unsigned t = atomicInc(&g_done, gridDim.x - 1);
        s_last = (t == gridDim.x - 1) ? 1 : 0;
    }
    __syncthreads();
    if (!s_last) return;

    // warps 0-7: warp w reduces acc rows w and (w+8 if w<4); warps 5-7 also counts
    {
        double v = g_accs[wid * SLOTS + lane] + g_accs[wid * SLOTS + 32 + lane];
        v = wredd(v);
        if (lane == 0) s_rows[wid] = v;
        if (wid < 4) {
            int row = wid + 8;
            double v2 = g_accs[row * SLOTS + lane] + g_accs[row * SLOTS + 32 + lane];
            v2 = wredd(v2);
            if (lane == 0) s_rows[row] = v2;
        }
        if (wid >= 5 && wid < 8) {
            int cr = wid - 5;
            int cv = g_cnts[cr * SLOTS + lane] + g_cnts[cr * SLOTS + 32 + lane];
            cv = wredi(cv);
            if (lane == 0) s_cnt[cr] = cv;
        }
    }
    __syncthreads();
    if (threadIdx.x == 0) {
        double Bn = (double)BB;
        double li_s = -s_rows[0] / Bn, lp_s = -(s_rows[1] + s_rows[2]) / Bn;
        double li_t = -s_rows[3] / Bn, lp_t = -(s_rows[4] + s_rows[5]) / Bn;
        double lt_s = -s_rows[6] / Bn, lt_t = -s_rows[7] / Bn;
        double cu = (double)(s_cnt[0] > 1 ? s_cnt[0] : 1);
        double cs = (double)(s_cnt[1] > 1 ? s_cnt[1] : 1);
        double ct = (double)(s_cnt[2] > 1 ? s_cnt[2] : 1);
        double dis = s_rows[8] / (cu * DD) + s_rows[9] / (cs * DD)
                   + s_rows[10] / (cu * DD) + s_rows[11] / (ct * DD);
        double loss = lt_s + lt_t + 0.1 * (li_s + li_t) + 0.1 * (lp_s + lp_t) - 0.01 * dis;
        out[0] = (float)loss;
    }
}

// ---------------- launch ----------------
extern "C" void kernel_launch(void* const* d_in, const int* in_sizes, int n_in,
                              void* d_out, int out_size) {
    const int* user = (const int*)d_in[0];
    const int* src_pos = (const int*)d_in[1];
    const int* src_neg = (const int*)d_in[2];
    const int* tgt_pos = (const int*)d_in[3];
    const int* tgt_neg = (const int*)d_in[4];
    const unsigned* mask_s = (const unsigned*)d_in[5];
    const unsigned* mask_t = (const unsigned*)d_in[6];
    const float* su_int = (const float*)d_in[7];
    const float* si_int = (const float*)d_in[8];
    const float* tu_int = (const float*)d_in[9];
    const float* ti_int = (const float*)d_in[10];
    const float* su_pop = (const float*)d_in[11];
    const float* si_pop = (const float*)d_in[12];
    const float* tu_pop = (const float*)d_in[13];
    const float* ti_pop = (const float*)d_in[14];
    const int* s_rows = (const int*)d_in[15];
    const int* s_cols = (const int*)d_in[16];
    const float* s_vals = (const float*)d_in[17];
    const int* t_rows = (const int*)d_in[18];
    const int* t_cols = (const int*)d_in[19];
    const float* t_vals = (const float*)d_in[20];
    const float* drop_s_int = (const float*)d_in[21];
    const float* drop_t_int = (const float*)d_in[22];
    const float* drop_s_pop = (const float*)d_in[23];
    const float* drop_t_pop = (const float*)d_in[24];

    int nnz_s = in_sizes[15];
    int nnz_t = in_sizes[18];
    int blocks_s = (nnz_s + 255) / 256;
    int blocks_t = (nnz_t + 255) / 256;

    k_clear<<<(NSW + 255) / 256, 256>>>();
    k_bitmap<<<(5 * BB + 255) / 256, 256>>>(user, src_pos, src_neg, tgt_pos, tgt_neg);
    k_zero_rows<<<(NSW + NTW + 7) / 8, 256>>>();
    k_edges_all<<<blocks_s + blocks_t, 256>>>(
        s_rows, s_cols, s_vals, drop_s_int, drop_s_pop,
        t_rows, t_cols, t_vals, drop_t_int, drop_t_pop,
        su_int, si_int, su_pop, si_pop,
        tu_int, ti_int, tu_pop, ti_pop,
        nnz_s, nnz_t, blocks_s);
    int dis_blocks = (U_CNT + SI_CNT + TI_CNT + 7) / 8;
    k_loss_dis_final<<<LOSS_BLOCKS + dis_blocks, 256>>>(
        user, src_pos, src_neg, tgt_pos, tgt_neg, mask_s, mask_t,
        su_int, si_int, tu_int, ti_int, su_pop, si_pop, tu_pop, ti_pop,
        (float*)d_out);
}